// round 6
// baseline (speedup 1.0000x reference)
#include <cuda_runtime.h>
#include <cstdint>

#define NV 4096
#define ALPHA 0.2f

// ---------------- device scratch ----------------
__device__ float g_Wh[NV * 64];
__device__ float g_e1[NV], g_e2[NV];
__device__ float g_E1[NV], g_E2[NV];
__device__ float g_A[NV], g_B[NV], g_thE[NV], g_dinv[NV];
__device__ float g_part[8][NV * 64];

// ---------------- K1: Wh = H@W + e1/e2 + E1/E2 (16-row blocks, grid 256) -----
__global__ __launch_bounds__(256) void k1_wh(const float* __restrict__ H,
                                             const float* __restrict__ W,
                                             const float* __restrict__ a) {
    __shared__ float Hs[16][68];
    __shared__ float Ws[64][64];
    int tid = threadIdx.x;
    int tr = tid >> 4;     // row 0..15
    int tc = tid & 15;     // col group of 4
    int row0 = blockIdx.x * 16;

    unsigned long long acc[2] = {0ull, 0ull};

    for (int kk = 0; kk < 256; kk += 64) {
#pragma unroll
        for (int t = 0; t < 4; t++) {
            int u = tid + t * 256;
            int r = u >> 4, c4 = u & 15;
            *(float4*)&Ws[r][c4 * 4] = *(const float4*)&W[(size_t)(kk + r) * 64 + c4 * 4];
        }
        *(float4*)&Hs[tr][tc * 4] = *(const float4*)&H[(size_t)(row0 + tr) * 256 + kk + tc * 4];
        __syncthreads();
#pragma unroll 8
        for (int k = 0; k < 64; k++) {
            float4 w4 = *(const float4*)&Ws[k][tc * 4];
            unsigned long long w01, w23, hp;
            asm("mov.b64 %0, {%1, %2};" : "=l"(w01) : "f"(w4.x), "f"(w4.y));
            asm("mov.b64 %0, {%1, %2};" : "=l"(w23) : "f"(w4.z), "f"(w4.w));
            float h = Hs[tr][k];
            asm("mov.b64 %0, {%1, %1};" : "=l"(hp) : "f"(h));
            asm("fma.rn.f32x2 %0, %1, %2, %0;" : "+l"(acc[0]) : "l"(hp), "l"(w01));
            asm("fma.rn.f32x2 %0, %1, %2, %0;" : "+l"(acc[1]) : "l"(hp), "l"(w23));
        }
        __syncthreads();
    }

    float v0 = __uint_as_float((uint32_t)acc[0]);
    float v1 = __uint_as_float((uint32_t)(acc[0] >> 32));
    float v2 = __uint_as_float((uint32_t)acc[1]);
    float v3 = __uint_as_float((uint32_t)(acc[1] >> 32));

    int i = row0 + tr;
    *(float4*)&g_Wh[(size_t)i * 64 + tc * 4] = make_float4(v0, v1, v2, v3);

    float p1 = v0 * __ldg(&a[tc * 4]) + v1 * __ldg(&a[tc * 4 + 1])
             + v2 * __ldg(&a[tc * 4 + 2]) + v3 * __ldg(&a[tc * 4 + 3]);
    float p2 = v0 * __ldg(&a[64 + tc * 4]) + v1 * __ldg(&a[64 + tc * 4 + 1])
             + v2 * __ldg(&a[64 + tc * 4 + 2]) + v3 * __ldg(&a[64 + tc * 4 + 3]);
#pragma unroll
    for (int off = 1; off < 16; off <<= 1) {
        p1 += __shfl_xor_sync(0xffffffffu, p1, off);
        p2 += __shfl_xor_sync(0xffffffffu, p2, off);
    }
    if (tc == 0) {
        g_e1[i] = p1;
        g_e2[i] = p2;
        g_E1[i] = __expf(p2);
        g_E2[i] = __expf(ALPHA * p2);
    }
}

// ---------------- K2: per-row m, A, B, thE, 1/denominator (smem-staged) ------
__global__ __launch_bounds__(256) void k2_denom() {
    __shared__ float sE1[NV];
    __shared__ float sE2[NV];
    __shared__ float red[8];
    int tid = threadIdx.x;
#pragma unroll
    for (int t = 0; t < 4; t++) {
        ((float4*)sE1)[tid + t * 256] = ((const float4*)g_E1)[tid + t * 256];
        ((float4*)sE2)[tid + t * 256] = ((const float4*)g_E2)[tid + t * 256];
    }
    float mx = -1e30f;
#pragma unroll
    for (int t = 0; t < 4; t++) {
        float4 v = ((const float4*)g_e2)[tid + t * 256];
        mx = fmaxf(fmaxf(mx, v.x), fmaxf(fmaxf(v.y, v.z), v.w));
    }
#pragma unroll
    for (int o = 16; o > 0; o >>= 1) mx = fmaxf(mx, __shfl_xor_sync(0xffffffffu, mx, o));
    if ((tid & 31) == 0) red[tid >> 5] = mx;
    __syncthreads();
    float e2max = red[0];
#pragma unroll
    for (int w = 1; w < 8; w++) e2max = fmaxf(e2max, red[w]);

    int il = tid >> 4;
    int sub = tid & 15;
    int i = blockIdx.x * 16 + il;
    float e1v = g_e1[i];
    float s = e1v + e2max;
    float m = s > 0.f ? s : ALPHA * s;
    float A = __expf(e1v - m);
    float B = __expf(ALPHA * e1v - m);
    float thE = __expf(-e1v);

    float d = 0.f;
#pragma unroll 4
    for (int t = 0; t < 64; t++) {
        int j = sub * 4 + t * 64;
        float4 E1v = *(const float4*)&sE1[j];
        float4 E2v = *(const float4*)&sE2[j];
        d += (E1v.x > thE) ? A * E1v.x : B * E2v.x;
        d += (E1v.y > thE) ? A * E1v.y : B * E2v.y;
        d += (E1v.z > thE) ? A * E1v.z : B * E2v.z;
        d += (E1v.w > thE) ? A * E1v.w : B * E2v.w;
    }
#pragma unroll
    for (int o = 8; o > 0; o >>= 1) d += __shfl_xor_sync(0xffffffffu, d, o);
    if (sub == 0) {
        g_A[i] = A; g_B[i] = B; g_thE[i] = thE;
        g_dinv[i] = 1.f / d;
    }
}

// ---------------- K3: masked weighted GEMM, 64i x 64c tiles, 128 threads -----
// Grid: 64 row-blocks (64 i) x 8 j-segments (512 j) = 512 CTAs, 128 thr,
// smem 36KB, target 4 CTAs/SM (12-16 warps/SM on every SM, single wave).
// Per thread: 8i x 4c; inner loop per j: 3 LDS.128 + 4 dup-movs + 16 FFMA2.
#define K3_SMEM 36864
__global__ __launch_bounds__(128, 4) void k3_main(const int* __restrict__ adj) {
    extern __shared__ float sm[];
    float* ws  = sm;            // [64][64] (j-major, i-contiguous)
    float* whs = sm + 4096;     // [64][64]
    float* sE1 = sm + 8192;     // [512]
    float* sE2 = sm + 8704;     // [512]

    int tid = threadIdx.x;
    int rb = blockIdx.x >> 3;          // 0..63
    int jseg = blockIdx.x & 7;         // 0..7
    int jbase = jseg << 9;             // *512

    ((float4*)sE1)[tid] = ((const float4*)(g_E1 + jbase))[tid];
    ((float4*)sE2)[tid] = ((const float4*)(g_E2 + jbase))[tid];

    // build role: row (0..63), j-half jh (32 j of the 64-j chunk)
    int row = tid & 63;
    int jh = (tid >> 6) * 32;
    int gi = rb * 64 + row;
    float Ai = __ldg(&g_A[gi]), Bi = __ldg(&g_B[gi]), th = __ldg(&g_thE[gi]);
    const int4* adjp = (const int4*)(adj + (size_t)gi * NV + jbase + jh);

    // compute role: rows tr*8..+7 (tr 0..7), cols tc*4..+3 (tc 0..15)
    int tr = tid >> 4;
    int tc = tid & 15;

    unsigned long long acc[16];
#pragma unroll
    for (int q = 0; q < 16; q++) acc[q] = 0ull;

    int4 pref[8];
#pragma unroll
    for (int q = 0; q < 8; q++) pref[q] = __ldg(adjp + q);

    for (int ch = 0; ch < 8; ++ch) {
        __syncthreads();   // prev chunk consumed (covers E staging on ch=0)

        // load Wh chunk: 64 rows x 64 cols (8 float4 per thread)
#pragma unroll
        for (int t = 0; t < 8; t++) {
            int u = tid + t * 128;
            int r = u >> 4, c4 = u & 15;
            *(float4*)&whs[r * 64 + c4 * 4] =
                *(const float4*)&g_Wh[(size_t)(jbase + ch * 64 + r) * 64 + c4 * 4];
        }
        // build masked-weight tile ws[j][i] from pref
#pragma unroll
        for (int q = 0; q < 8; q++) {
            int4 av = pref[q];
            int jl = ch * 64 + jh + q * 4;
            float4 e1 = *(const float4*)&sE1[jl];
            float4 e2 = *(const float4*)&sE2[jl];
            float w0 = (av.x > 0) ? ((e1.x > th) ? Ai * e1.x : Bi * e2.x) : 0.f;
            float w1 = (av.y > 0) ? ((e1.y > th) ? Ai * e1.y : Bi * e2.y) : 0.f;
            float w2 = (av.z > 0) ? ((e1.z > th) ? Ai * e1.z : Bi * e2.z) : 0.f;
            float w3 = (av.w > 0) ? ((e1.w > th) ? Ai * e1.w : Bi * e2.w) : 0.f;
            int jr = (jh + q * 4) * 64 + row;
            ws[jr]       = w0;
            ws[jr + 64]  = w1;
            ws[jr + 128] = w2;
            ws[jr + 192] = w3;
        }
        if (ch < 7) {
#pragma unroll
            for (int q = 0; q < 8; q++) pref[q] = __ldg(adjp + (ch + 1) * 16 + q);
        }
        __syncthreads();

#pragma unroll 4
        for (int jj = 0; jj < 64; jj++) {
            ulonglong2 wA = *(const ulonglong2*)&ws[jj * 64 + tr * 8];
            ulonglong2 wB = *(const ulonglong2*)&ws[jj * 64 + tr * 8 + 4];
            float4 wh = *(const float4*)&whs[jj * 64 + tc * 4];
            unsigned long long d0, d1, d2, d3;
            asm("mov.b64 %0, {%1, %1};" : "=l"(d0) : "f"(wh.x));
            asm("mov.b64 %0, {%1, %1};" : "=l"(d1) : "f"(wh.y));
            asm("mov.b64 %0, {%1, %1};" : "=l"(d2) : "f"(wh.z));
            asm("mov.b64 %0, {%1, %1};" : "=l"(d3) : "f"(wh.w));
            asm("fma.rn.f32x2 %0, %1, %2, %0;" : "+l"(acc[0])  : "l"(wA.x), "l"(d0));
            asm("fma.rn.f32x2 %0, %1, %2, %0;" : "+l"(acc[1])  : "l"(wA.x), "l"(d1));
            asm("fma.rn.f32x2 %0, %1, %2, %0;" : "+l"(acc[2])  : "l"(wA.x), "l"(d2));
            asm("fma.rn.f32x2 %0, %1, %2, %0;" : "+l"(acc[3])  : "l"(wA.x), "l"(d3));
            asm("fma.rn.f32x2 %0, %1, %2, %0;" : "+l"(acc[4])  : "l"(wA.y), "l"(d0));
            asm("fma.rn.f32x2 %0, %1, %2, %0;" : "+l"(acc[5])  : "l"(wA.y), "l"(d1));
            asm("fma.rn.f32x2 %0, %1, %2, %0;" : "+l"(acc[6])  : "l"(wA.y), "l"(d2));
            asm("fma.rn.f32x2 %0, %1, %2, %0;" : "+l"(acc[7])  : "l"(wA.y), "l"(d3));
            asm("fma.rn.f32x2 %0, %1, %2, %0;" : "+l"(acc[8])  : "l"(wB.x), "l"(d0));
            asm("fma.rn.f32x2 %0, %1, %2, %0;" : "+l"(acc[9])  : "l"(wB.x), "l"(d1));
            asm("fma.rn.f32x2 %0, %1, %2, %0;" : "+l"(acc[10]) : "l"(wB.x), "l"(d2));
            asm("fma.rn.f32x2 %0, %1, %2, %0;" : "+l"(acc[11]) : "l"(wB.x), "l"(d3));
            asm("fma.rn.f32x2 %0, %1, %2, %0;" : "+l"(acc[12]) : "l"(wB.y), "l"(d0));
            asm("fma.rn.f32x2 %0, %1, %2, %0;" : "+l"(acc[13]) : "l"(wB.y), "l"(d1));
            asm("fma.rn.f32x2 %0, %1, %2, %0;" : "+l"(acc[14]) : "l"(wB.y), "l"(d2));
            asm("fma.rn.f32x2 %0, %1, %2, %0;" : "+l"(acc[15]) : "l"(wB.y), "l"(d3));
        }
    }

    // write partials
    float* base = &g_part[jseg][(size_t)(rb * 64 + tr * 8) * 64 + tc * 4];
#pragma unroll
    for (int ip = 0; ip < 4; ip++) {
        float4 lo, hi;
        lo.x = __uint_as_float((uint32_t)acc[ip * 4 + 0]);
        lo.y = __uint_as_float((uint32_t)acc[ip * 4 + 1]);
        lo.z = __uint_as_float((uint32_t)acc[ip * 4 + 2]);
        lo.w = __uint_as_float((uint32_t)acc[ip * 4 + 3]);
        hi.x = __uint_as_float((uint32_t)(acc[ip * 4 + 0] >> 32));
        hi.y = __uint_as_float((uint32_t)(acc[ip * 4 + 1] >> 32));
        hi.z = __uint_as_float((uint32_t)(acc[ip * 4 + 2] >> 32));
        hi.w = __uint_as_float((uint32_t)(acc[ip * 4 + 3] >> 32));
        *(float4*)(base + (ip * 2) * 64)     = lo;
        *(float4*)(base + (ip * 2 + 1) * 64) = hi;
    }
}

// ---------------- K4: combine 8 partials, scale, ELU (vectorized) -----------
__global__ __launch_bounds__(256) void k4_out(float* __restrict__ out) {
    int v4 = blockIdx.x * 256 + threadIdx.x;
    float4 s = ((const float4*)g_part[0])[v4];
#pragma unroll
    for (int p = 1; p < 8; p++) {
        float4 t = ((const float4*)g_part[p])[v4];
        s.x += t.x; s.y += t.y; s.z += t.z; s.w += t.w;
    }
    int i = v4 >> 4;
    float di = g_dinv[i];
    s.x *= di; s.y *= di; s.z *= di; s.w *= di;
    s.x = s.x > 0.f ? s.x : (__expf(s.x) - 1.f);
    s.y = s.y > 0.f ? s.y : (__expf(s.y) - 1.f);
    s.z = s.z > 0.f ? s.z : (__expf(s.z) - 1.f);
    s.w = s.w > 0.f ? s.w : (__expf(s.w) - 1.f);
    ((float4*)out)[v4] = s;
}

// ---------------- launch ----------------
extern "C" void kernel_launch(void* const* d_in, const int* in_sizes, int n_in,
                              void* d_out, int out_size) {
    const float* H = (const float*)d_in[0];
    const int* adj = (const int*)d_in[1];
    const float* W = (const float*)d_in[2];
    const float* a = (const float*)d_in[3];
    float* out = (float*)d_out;

    cudaFuncSetAttribute(k3_main, cudaFuncAttributeMaxDynamicSharedMemorySize, K3_SMEM);

    k1_wh<<<256, 256>>>(H, W, a);
    k2_denom<<<256, 256>>>();
    k3_main<<<512, 128, K3_SMEM>>>(adj);
    k4_out<<<256, 256>>>(out);
}

// round 7
// speedup vs baseline: 1.0003x; 1.0003x over previous
#include <cuda_runtime.h>
#include <cstdint>

#define NV 4096
#define ALPHA 0.2f

// ---------------- device scratch ----------------
__device__ float g_Wh[NV * 64];
__device__ float g_e1[NV], g_e2[NV];
__device__ float g_E1[NV], g_E2[NV];
__device__ float g_A[NV], g_B[NV], g_thE[NV], g_dinv[NV];
__device__ float g_part[32][NV * 64];
__device__ int g_tick;

__device__ __forceinline__ uint32_t smem_u32(const void* p) {
    uint32_t a;
    asm("{ .reg .u64 t; cvta.to.shared.u64 t, %1; cvt.u32.u64 %0, t; }" : "=r"(a) : "l"(p));
    return a;
}
__device__ __forceinline__ void cp16(uint32_t dst, const void* src) {
    asm volatile("cp.async.cg.shared.global [%0], [%1], 16;" :: "r"(dst), "l"(src));
}

// ---------------- K1: Wh = H@W + e1/e2 + E1/E2 (16-row blocks, grid 256) -----
__global__ __launch_bounds__(256) void k1_wh(const float* __restrict__ H,
                                             const float* __restrict__ W,
                                             const float* __restrict__ a) {
    __shared__ float Hs[16][68];
    __shared__ float Ws[64][64];
    int tid = threadIdx.x;
    int tr = tid >> 4;
    int tc = tid & 15;
    int row0 = blockIdx.x * 16;

    unsigned long long acc[2] = {0ull, 0ull};

    for (int kk = 0; kk < 256; kk += 64) {
#pragma unroll
        for (int t = 0; t < 4; t++) {
            int u = tid + t * 256;
            int r = u >> 4, c4 = u & 15;
            *(float4*)&Ws[r][c4 * 4] = *(const float4*)&W[(size_t)(kk + r) * 64 + c4 * 4];
        }
        *(float4*)&Hs[tr][tc * 4] = *(const float4*)&H[(size_t)(row0 + tr) * 256 + kk + tc * 4];
        __syncthreads();
#pragma unroll 8
        for (int k = 0; k < 64; k++) {
            float4 w4 = *(const float4*)&Ws[k][tc * 4];
            unsigned long long w01, w23, hp;
            asm("mov.b64 %0, {%1, %2};" : "=l"(w01) : "f"(w4.x), "f"(w4.y));
            asm("mov.b64 %0, {%1, %2};" : "=l"(w23) : "f"(w4.z), "f"(w4.w));
            float h = Hs[tr][k];
            asm("mov.b64 %0, {%1, %1};" : "=l"(hp) : "f"(h));
            asm("fma.rn.f32x2 %0, %1, %2, %0;" : "+l"(acc[0]) : "l"(hp), "l"(w01));
            asm("fma.rn.f32x2 %0, %1, %2, %0;" : "+l"(acc[1]) : "l"(hp), "l"(w23));
        }
        __syncthreads();
    }

    float v0 = __uint_as_float((uint32_t)acc[0]);
    float v1 = __uint_as_float((uint32_t)(acc[0] >> 32));
    float v2 = __uint_as_float((uint32_t)acc[1]);
    float v3 = __uint_as_float((uint32_t)(acc[1] >> 32));

    int i = row0 + tr;
    *(float4*)&g_Wh[(size_t)i * 64 + tc * 4] = make_float4(v0, v1, v2, v3);

    float p1 = v0 * __ldg(&a[tc * 4]) + v1 * __ldg(&a[tc * 4 + 1])
             + v2 * __ldg(&a[tc * 4 + 2]) + v3 * __ldg(&a[tc * 4 + 3]);
    float p2 = v0 * __ldg(&a[64 + tc * 4]) + v1 * __ldg(&a[64 + tc * 4 + 1])
             + v2 * __ldg(&a[64 + tc * 4 + 2]) + v3 * __ldg(&a[64 + tc * 4 + 3]);
#pragma unroll
    for (int off = 1; off < 16; off <<= 1) {
        p1 += __shfl_xor_sync(0xffffffffu, p1, off);
        p2 += __shfl_xor_sync(0xffffffffu, p2, off);
    }
    if (tc == 0) {
        g_e1[i] = p1;
        g_e2[i] = p2;
        g_E1[i] = __expf(p2);
        g_E2[i] = __expf(ALPHA * p2);
    }
}

// ---------------- K2: per-row m, A, B, thE, 1/denominator ----------------
__global__ __launch_bounds__(256) void k2_denom() {
    __shared__ float sE1[NV];
    __shared__ float sE2[NV];
    __shared__ float red[8];
    int tid = threadIdx.x;
    if (blockIdx.x == 0 && tid == 0) g_tick = 0;   // reset k3 ticket each launch
#pragma unroll
    for (int t = 0; t < 4; t++) {
        ((float4*)sE1)[tid + t * 256] = ((const float4*)g_E1)[tid + t * 256];
        ((float4*)sE2)[tid + t * 256] = ((const float4*)g_E2)[tid + t * 256];
    }
    float mx = -1e30f;
#pragma unroll
    for (int t = 0; t < 4; t++) {
        float4 v = ((const float4*)g_e2)[tid + t * 256];
        mx = fmaxf(fmaxf(mx, v.x), fmaxf(fmaxf(v.y, v.z), v.w));
    }
#pragma unroll
    for (int o = 16; o > 0; o >>= 1) mx = fmaxf(mx, __shfl_xor_sync(0xffffffffu, mx, o));
    if ((tid & 31) == 0) red[tid >> 5] = mx;
    __syncthreads();
    float e2max = red[0];
#pragma unroll
    for (int w = 1; w < 8; w++) e2max = fmaxf(e2max, red[w]);

    int il = tid >> 4;
    int sub = tid & 15;
    int i = blockIdx.x * 16 + il;
    float e1v = g_e1[i];
    float s = e1v + e2max;
    float m = s > 0.f ? s : ALPHA * s;
    float A = __expf(e1v - m);
    float B = __expf(ALPHA * e1v - m);
    float thE = __expf(-e1v);

    float d = 0.f;
#pragma unroll 4
    for (int t = 0; t < 64; t++) {
        int j = sub * 4 + t * 64;
        float4 E1v = *(const float4*)&sE1[j];
        float4 E2v = *(const float4*)&sE2[j];
        d += (E1v.x > thE) ? A * E1v.x : B * E2v.x;
        d += (E1v.y > thE) ? A * E1v.y : B * E2v.y;
        d += (E1v.z > thE) ? A * E1v.z : B * E2v.z;
        d += (E1v.w > thE) ? A * E1v.w : B * E2v.w;
    }
#pragma unroll
    for (int o = 8; o > 0; o >>= 1) d += __shfl_xor_sync(0xffffffffu, d, o);
    if (sub == 0) {
        g_A[i] = A; g_B[i] = B; g_thE[i] = thE;
        g_dinv[i] = 1.f / d;
    }
}

// ---------------- K3: persistent masked weighted GEMM ----------------
// 296 persistent CTAs (2/SM), 256 threads; dynamic ticket over 1024 tiles
// of 128i x 128j (2 chunks of 64 j). Double-buffered ws + whs (cp.async),
// ONE sync per chunk. Per thread: 8i x 4c; per j: 3 LDS.128 + 4 movs + 16 FFMA2.
// smem floats: ws[2][64*128] @0, whs[2][64*64] @16384 -> 96KB
#define K3_SMEM 98304
__global__ __launch_bounds__(256, 2) void k3_main(const int* __restrict__ adj) {
    extern __shared__ float sm[];
    __shared__ int s_t;
    uint32_t sb = smem_u32(sm);
    int tid = threadIdx.x;

    // build role
    int bi = tid & 127;
    int jh = (tid >> 7) * 32;
    // compute role
    int tr = tid >> 4;
    int tc = tid & 15;

    for (;;) {
        if (tid == 0) s_t = atomicAdd(&g_tick, 1);
        __syncthreads();            // tile boundary: ticket + protect smem reuse
        int t = s_t;
        if (t >= 1024) break;
        int rb = t >> 5;
        int jt = t & 31;
        int jbase = jt << 7;

        int gi = rb * 128 + bi;
        float Ai = __ldg(&g_A[gi]), Bi = __ldg(&g_B[gi]), th = __ldg(&g_thE[gi]);
        const int4* adjp = (const int4*)(adj + (size_t)gi * NV + jbase + jh);

        unsigned long long acc[16];
#pragma unroll
        for (int q = 0; q < 16; q++) acc[q] = 0ull;

        // ---- prologue: chunk 0 ----
        int4 pref[8];
#pragma unroll
        for (int q = 0; q < 8; q++) pref[q] = __ldg(adjp + q);
        {   // cp.async whs[0] <- Wh rows jbase..jbase+63
            uint32_t base = sb + (16384u + 0u) * 4u;
#pragma unroll
            for (int q = 0; q < 4; q++) {
                int u = tid + q * 256;
                int r = u >> 4, c4 = u & 15;
                cp16(base + (uint32_t)(r * 64 + c4 * 4) * 4u,
                     &g_Wh[(size_t)(jbase + r) * 64 + c4 * 4]);
            }
            asm volatile("cp.async.commit_group;" ::: "memory");
        }
#pragma unroll
        for (int q = 0; q < 8; q++) {   // build ws[0]
            int4 av = pref[q];
            int jl = jbase + jh + q * 4;
            float4 e1 = __ldg((const float4*)&g_E1[jl]);
            float4 e2 = __ldg((const float4*)&g_E2[jl]);
            float w0 = (av.x > 0) ? ((e1.x > th) ? Ai * e1.x : Bi * e2.x) : 0.f;
            float w1 = (av.y > 0) ? ((e1.y > th) ? Ai * e1.y : Bi * e2.y) : 0.f;
            float w2 = (av.z > 0) ? ((e1.z > th) ? Ai * e1.z : Bi * e2.z) : 0.f;
            float w3 = (av.w > 0) ? ((e1.w > th) ? Ai * e1.w : Bi * e2.w) : 0.f;
            int jr = (jh + q * 4) * 128 + bi;
            sm[jr]       = w0;
            sm[jr + 128] = w1;
            sm[jr + 256] = w2;
            sm[jr + 384] = w3;
        }
#pragma unroll
        for (int q = 0; q < 8; q++) pref[q] = __ldg(adjp + 16 + q);   // chunk-1 adj
        asm volatile("cp.async.wait_group 0;" ::: "memory");
        __syncthreads();

        // ---- chunk 0 compute, chunk 1 build (overlapped via warp skew) ----
        {   // cp.async whs[1] <- Wh rows jbase+64..jbase+127
            uint32_t base = sb + (16384u + 4096u) * 4u;
#pragma unroll
            for (int q = 0; q < 4; q++) {
                int u = tid + q * 256;
                int r = u >> 4, c4 = u & 15;
                cp16(base + (uint32_t)(r * 64 + c4 * 4) * 4u,
                     &g_Wh[(size_t)(jbase + 64 + r) * 64 + c4 * 4]);
            }
            asm volatile("cp.async.commit_group;" ::: "memory");
        }
#pragma unroll
        for (int q = 0; q < 8; q++) {   // build ws[1]
            int4 av = pref[q];
            int jl = jbase + 64 + jh + q * 4;
            float4 e1 = __ldg((const float4*)&g_E1[jl]);
            float4 e2 = __ldg((const float4*)&g_E2[jl]);
            float w0 = (av.x > 0) ? ((e1.x > th) ? Ai * e1.x : Bi * e2.x) : 0.f;
            float w1 = (av.y > 0) ? ((e1.y > th) ? Ai * e1.y : Bi * e2.y) : 0.f;
            float w2 = (av.z > 0) ? ((e1.z > th) ? Ai * e1.z : Bi * e2.z) : 0.f;
            float w3 = (av.w > 0) ? ((e1.w > th) ? Ai * e1.w : Bi * e2.w) : 0.f;
            int jr = 8192 + (jh + q * 4) * 128 + bi;
            sm[jr]       = w0;
            sm[jr + 128] = w1;
            sm[jr + 256] = w2;
            sm[jr + 384] = w3;
        }
        // compute chunk 0
#pragma unroll
        for (int half = 0; half < 2; half++) {
            const float* ws  = sm + half * 8192;
            const float* whs = sm + 16384 + half * 4096;
#pragma unroll 4
            for (int jj = 0; jj < 64; jj++) {
                ulonglong2 wA = *(const ulonglong2*)&ws[jj * 128 + tr * 8];
                ulonglong2 wB = *(const ulonglong2*)&ws[jj * 128 + tr * 8 + 4];
                float4 wh = *(const float4*)&whs[jj * 64 + tc * 4];
                unsigned long long d0, d1, d2, d3;
                asm("mov.b64 %0, {%1, %1};" : "=l"(d0) : "f"(wh.x));
                asm("mov.b64 %0, {%1, %1};" : "=l"(d1) : "f"(wh.y));
                asm("mov.b64 %0, {%1, %1};" : "=l"(d2) : "f"(wh.z));
                asm("mov.b64 %0, {%1, %1};" : "=l"(d3) : "f"(wh.w));
                asm("fma.rn.f32x2 %0, %1, %2, %0;" : "+l"(acc[0])  : "l"(wA.x), "l"(d0));
                asm("fma.rn.f32x2 %0, %1, %2, %0;" : "+l"(acc[1])  : "l"(wA.x), "l"(d1));
                asm("fma.rn.f32x2 %0, %1, %2, %0;" : "+l"(acc[2])  : "l"(wA.x), "l"(d2));
                asm("fma.rn.f32x2 %0, %1, %2, %0;" : "+l"(acc[3])  : "l"(wA.x), "l"(d3));
                asm("fma.rn.f32x2 %0, %1, %2, %0;" : "+l"(acc[4])  : "l"(wA.y), "l"(d0));
                asm("fma.rn.f32x2 %0, %1, %2, %0;" : "+l"(acc[5])  : "l"(wA.y), "l"(d1));
                asm("fma.rn.f32x2 %0, %1, %2, %0;" : "+l"(acc[6])  : "l"(wA.y), "l"(d2));
                asm("fma.rn.f32x2 %0, %1, %2, %0;" : "+l"(acc[7])  : "l"(wA.y), "l"(d3));
                asm("fma.rn.f32x2 %0, %1, %2, %0;" : "+l"(acc[8])  : "l"(wB.x), "l"(d0));
                asm("fma.rn.f32x2 %0, %1, %2, %0;" : "+l"(acc[9])  : "l"(wB.x), "l"(d1));
                asm("fma.rn.f32x2 %0, %1, %2, %0;" : "+l"(acc[10]) : "l"(wB.x), "l"(d2));
                asm("fma.rn.f32x2 %0, %1, %2, %0;" : "+l"(acc[11]) : "l"(wB.x), "l"(d3));
                asm("fma.rn.f32x2 %0, %1, %2, %0;" : "+l"(acc[12]) : "l"(wB.y), "l"(d0));
                asm("fma.rn.f32x2 %0, %1, %2, %0;" : "+l"(acc[13]) : "l"(wB.y), "l"(d1));
                asm("fma.rn.f32x2 %0, %1, %2, %0;" : "+l"(acc[14]) : "l"(wB.y), "l"(d2));
                asm("fma.rn.f32x2 %0, %1, %2, %0;" : "+l"(acc[15]) : "l"(wB.y), "l"(d3));
            }
            if (half == 0) {   // chunk-1 tiles must be fully built & loaded
                asm volatile("cp.async.wait_group 0;" ::: "memory");
                __syncthreads();
            }
        }

        // write partials for this tile
        float* base = &g_part[jt][(size_t)(rb * 128 + tr * 8) * 64 + tc * 4];
#pragma unroll
        for (int ip = 0; ip < 4; ip++) {
            float4 lo, hi;
            lo.x = __uint_as_float((uint32_t)acc[ip * 4 + 0]);
            lo.y = __uint_as_float((uint32_t)acc[ip * 4 + 1]);
            lo.z = __uint_as_float((uint32_t)acc[ip * 4 + 2]);
            lo.w = __uint_as_float((uint32_t)acc[ip * 4 + 3]);
            hi.x = __uint_as_float((uint32_t)(acc[ip * 4 + 0] >> 32));
            hi.y = __uint_as_float((uint32_t)(acc[ip * 4 + 1] >> 32));
            hi.z = __uint_as_float((uint32_t)(acc[ip * 4 + 2] >> 32));
            hi.w = __uint_as_float((uint32_t)(acc[ip * 4 + 3] >> 32));
            *(float4*)(base + (ip * 2) * 64)     = lo;
            *(float4*)(base + (ip * 2 + 1) * 64) = hi;
        }
    }
}

// ---------------- K4: combine 32 partials, scale, ELU ----------------
__global__ __launch_bounds__(256) void k4_out(float* __restrict__ out) {
    int v4 = blockIdx.x * 256 + threadIdx.x;
    float4 s = __ldg(&((const float4*)g_part[0])[v4]);
#pragma unroll
    for (int p = 1; p < 32; p++) {
        float4 t = __ldg(&((const float4*)g_part[p])[v4]);
        s.x += t.x; s.y += t.y; s.z += t.z; s.w += t.w;
    }
    int i = v4 >> 4;
    float di = g_dinv[i];
    s.x *= di; s.y *= di; s.z *= di; s.w *= di;
    s.x = s.x > 0.f ? s.x : (__expf(s.x) - 1.f);
    s.y = s.y > 0.f ? s.y : (__expf(s.y) - 1.f);
    s.z = s.z > 0.f ? s.z : (__expf(s.z) - 1.f);
    s.w = s.w > 0.f ? s.w : (__expf(s.w) - 1.f);
    ((float4*)out)[v4] = s;
}

// ---------------- launch ----------------
extern "C" void kernel_launch(void* const* d_in, const int* in_sizes, int n_in,
                              void* d_out, int out_size) {
    const float* H = (const float*)d_in[0];
    const int* adj = (const int*)d_in[1];
    const float* W = (const float*)d_in[2];
    const float* a = (const float*)d_in[3];
    float* out = (float*)d_out;

    cudaFuncSetAttribute(k3_main, cudaFuncAttributeMaxDynamicSharedMemorySize, K3_SMEM);

    k1_wh<<<256, 256>>>(H, W, a);
    k2_denom<<<256, 256>>>();
    k3_main<<<296, 256, K3_SMEM>>>(adj);
    k4_out<<<256, 256>>>(out);
}

// round 8
// speedup vs baseline: 1.2830x; 1.2826x over previous
#include <cuda_runtime.h>
#include <cstdint>

#define NV 4096
#define ALPHA 0.2f

// ---------------- device scratch ----------------
__device__ float g_Wh[NV * 64];
__device__ float g_e1[NV], g_e2[NV];
__device__ float g_E1[NV], g_E2[NV];
__device__ float g_A[NV], g_B[NV], g_thE[NV], g_dinv[NV];
__device__ float g_part[8][NV * 64];
__device__ uint2 g_WhC[64 * (NV / 2)];   // [c][j/2] = {bf16x2 hi pair, bf16x2 lo pair}

// ---------------- K1: Wh = H@W + e1/e2 + E1/E2 (16-row blocks, grid 256) -----
__global__ __launch_bounds__(256) void k1_wh(const float* __restrict__ H,
                                             const float* __restrict__ W,
                                             const float* __restrict__ a) {
    __shared__ float Hs[16][68];
    __shared__ float Ws[64][64];
    int tid = threadIdx.x;
    int tr = tid >> 4;
    int tc = tid & 15;
    int row0 = blockIdx.x * 16;

    unsigned long long acc[2] = {0ull, 0ull};

    for (int kk = 0; kk < 256; kk += 64) {
#pragma unroll
        for (int t = 0; t < 4; t++) {
            int u = tid + t * 256;
            int r = u >> 4, c4 = u & 15;
            *(float4*)&Ws[r][c4 * 4] = *(const float4*)&W[(size_t)(kk + r) * 64 + c4 * 4];
        }
        *(float4*)&Hs[tr][tc * 4] = *(const float4*)&H[(size_t)(row0 + tr) * 256 + kk + tc * 4];
        __syncthreads();
#pragma unroll 8
        for (int k = 0; k < 64; k++) {
            float4 w4 = *(const float4*)&Ws[k][tc * 4];
            unsigned long long w01, w23, hp;
            asm("mov.b64 %0, {%1, %2};" : "=l"(w01) : "f"(w4.x), "f"(w4.y));
            asm("mov.b64 %0, {%1, %2};" : "=l"(w23) : "f"(w4.z), "f"(w4.w));
            float h = Hs[tr][k];
            asm("mov.b64 %0, {%1, %1};" : "=l"(hp) : "f"(h));
            asm("fma.rn.f32x2 %0, %1, %2, %0;" : "+l"(acc[0]) : "l"(hp), "l"(w01));
            asm("fma.rn.f32x2 %0, %1, %2, %0;" : "+l"(acc[1]) : "l"(hp), "l"(w23));
        }
        __syncthreads();
    }

    float v0 = __uint_as_float((uint32_t)acc[0]);
    float v1 = __uint_as_float((uint32_t)(acc[0] >> 32));
    float v2 = __uint_as_float((uint32_t)acc[1]);
    float v3 = __uint_as_float((uint32_t)(acc[1] >> 32));

    int i = row0 + tr;
    *(float4*)&g_Wh[(size_t)i * 64 + tc * 4] = make_float4(v0, v1, v2, v3);

    float p1 = v0 * __ldg(&a[tc * 4]) + v1 * __ldg(&a[tc * 4 + 1])
             + v2 * __ldg(&a[tc * 4 + 2]) + v3 * __ldg(&a[tc * 4 + 3]);
    float p2 = v0 * __ldg(&a[64 + tc * 4]) + v1 * __ldg(&a[64 + tc * 4 + 1])
             + v2 * __ldg(&a[64 + tc * 4 + 2]) + v3 * __ldg(&a[64 + tc * 4 + 3]);
#pragma unroll
    for (int off = 1; off < 16; off <<= 1) {
        p1 += __shfl_xor_sync(0xffffffffu, p1, off);
        p2 += __shfl_xor_sync(0xffffffffu, p2, off);
    }
    if (tc == 0) {
        g_e1[i] = p1;
        g_e2[i] = p2;
        g_E1[i] = __expf(p2);
        g_E2[i] = __expf(ALPHA * p2);
    }
}

// ---------------- kT: transpose + bf16 hi/lo split of Wh -> g_WhC ------------
__global__ __launch_bounds__(256) void kT_split() {
    __shared__ float t[64][65];
    int tid = threadIdx.x;
    int j0 = blockIdx.x * 64;
#pragma unroll
    for (int q = 0; q < 4; q++) {
        int u = tid + q * 256;
        int r = u >> 4, c4 = u & 15;
        float4 vv = *(const float4*)&g_Wh[(size_t)(j0 + r) * 64 + c4 * 4];
        t[r][c4 * 4 + 0] = vv.x; t[r][c4 * 4 + 1] = vv.y;
        t[r][c4 * 4 + 2] = vv.z; t[r][c4 * 4 + 3] = vv.w;
    }
    __syncthreads();
    int c = tid >> 2;            // column 0..63
    int jq = (tid & 3) * 16;     // 16 j's per thread
    uint2 outv[8];
#pragma unroll
    for (int s = 0; s < 8; s++) {
        float w0 = t[jq + s * 2 + 0][c];
        float w1 = t[jq + s * 2 + 1][c];
        uint32_t hp;
        asm("cvt.rn.bf16x2.f32 %0, %1, %2;" : "=r"(hp) : "f"(w1), "f"(w0));
        float h0 = __uint_as_float(hp << 16);
        float h1 = __uint_as_float(hp & 0xffff0000u);
        float l0 = w0 - h0, l1 = w1 - h1;
        uint32_t lp;
        asm("cvt.rn.bf16x2.f32 %0, %1, %2;" : "=r"(lp) : "f"(l1), "f"(l0));
        outv[s] = make_uint2(hp, lp);
    }
    uint2* dst = &g_WhC[(size_t)c * (NV / 2) + ((j0 + jq) >> 1)];
#pragma unroll
    for (int s = 0; s < 8; s++) dst[s] = outv[s];
}

// ---------------- K2: per-row m, A, B, thE, 1/denominator ----------------
__global__ __launch_bounds__(256) void k2_denom() {
    __shared__ float sE1[NV];
    __shared__ float sE2[NV];
    __shared__ float red[8];
    int tid = threadIdx.x;
#pragma unroll
    for (int t = 0; t < 4; t++) {
        ((float4*)sE1)[tid + t * 256] = ((const float4*)g_E1)[tid + t * 256];
        ((float4*)sE2)[tid + t * 256] = ((const float4*)g_E2)[tid + t * 256];
    }
    float mx = -1e30f;
#pragma unroll
    for (int t = 0; t < 4; t++) {
        float4 v = ((const float4*)g_e2)[tid + t * 256];
        mx = fmaxf(fmaxf(mx, v.x), fmaxf(fmaxf(v.y, v.z), v.w));
    }
#pragma unroll
    for (int o = 16; o > 0; o >>= 1) mx = fmaxf(mx, __shfl_xor_sync(0xffffffffu, mx, o));
    if ((tid & 31) == 0) red[tid >> 5] = mx;
    __syncthreads();
    float e2max = red[0];
#pragma unroll
    for (int w = 1; w < 8; w++) e2max = fmaxf(e2max, red[w]);

    int il = tid >> 4;
    int sub = tid & 15;
    int i = blockIdx.x * 16 + il;
    float e1v = g_e1[i];
    float s = e1v + e2max;
    float m = s > 0.f ? s : ALPHA * s;
    float A = __expf(e1v - m);
    float B = __expf(ALPHA * e1v - m);
    float thE = __expf(-e1v);

    float d = 0.f;
#pragma unroll 4
    for (int t = 0; t < 64; t++) {
        int j = sub * 4 + t * 64;
        float4 E1v = *(const float4*)&sE1[j];
        float4 E2v = *(const float4*)&sE2[j];
        d += (E1v.x > thE) ? A * E1v.x : B * E2v.x;
        d += (E1v.y > thE) ? A * E1v.y : B * E2v.y;
        d += (E1v.z > thE) ? A * E1v.z : B * E2v.z;
        d += (E1v.w > thE) ? A * E1v.w : B * E2v.w;
    }
#pragma unroll
    for (int o = 8; o > 0; o >>= 1) d += __shfl_xor_sync(0xffffffffu, d, o);
    if (sub == 0) {
        g_A[i] = A; g_B[i] = B; g_thE[i] = thE;
        g_dinv[i] = 1.f / d;
    }
}

// ---------------- A-fragment pair build: masked weight -> bf16 hi/lo ---------
__device__ __forceinline__ void build_pair(int ax, int ay,
                                           float e1x, float e1y,
                                           float e2x, float e2y,
                                           float Ai, float Bi, float th,
                                           uint32_t& hi, uint32_t& lo) {
    float w0 = (ax > 0) ? ((e1x > th) ? Ai * e1x : Bi * e2x) : 0.f;
    float w1 = (ay > 0) ? ((e1y > th) ? Ai * e1y : Bi * e2y) : 0.f;
    uint32_t h;
    asm("cvt.rn.bf16x2.f32 %0, %1, %2;" : "=r"(h) : "f"(w1), "f"(w0));
    float h0 = __uint_as_float(h << 16);
    float h1 = __uint_as_float(h & 0xffff0000u);
    float l0 = w0 - h0, l1 = w1 - h1;
    uint32_t l;
    asm("cvt.rn.bf16x2.f32 %0, %1, %2;" : "=r"(l) : "f"(l1), "f"(l0));
    hi = h; lo = l;
}

#define MMA_BF16(c0, c1, c2, c3, a0, a1, a2, a3, b0, b1)                        \
    asm("mma.sync.aligned.m16n8k16.row.col.f32.bf16.bf16.f32 "                 \
        "{%0,%1,%2,%3}, {%4,%5,%6,%7}, {%8,%9}, {%0,%1,%2,%3};"                \
        : "+f"(c0), "+f"(c1), "+f"(c2), "+f"(c3)                               \
        : "r"(a0), "r"(a1), "r"(a2), "r"(a3), "r"(b0), "r"(b1))

// ---------------- K3: masked GEMM on legacy tensor cores (bf16 hi/lo) --------
// Grid 256 = 32 rb (128 i) x 8 jseg (512 j). 8 warps/CTA, warp = 16 rows.
// 32 k-tiles of 16 j. Per k-tile per warp: build A frags in registers (adj int2
// + factored exps), B frags via LDG.64 from interleaved g_WhC, 8 n-tiles x 3 mma.
#define JSEG 512
__global__ __launch_bounds__(256, 2) void k3_main(const int* __restrict__ adj) {
    __shared__ float sE1[JSEG], sE2[JSEG];
    int tid = threadIdx.x;
    int warp = tid >> 5, lane = tid & 31;
    int gid = lane >> 2, tg = lane & 3;
    int rb = blockIdx.x >> 3;
    int jseg = blockIdx.x & 7;
    int jbase = jseg * JSEG;

    ((float2*)sE1)[tid] = __ldg(&((const float2*)(g_E1 + jbase))[tid]);
    ((float2*)sE2)[tid] = __ldg(&((const float2*)(g_E2 + jbase))[tid]);
    __syncthreads();

    int r0 = rb * 128 + warp * 16 + gid;
    int r1 = r0 + 8;
    float Ai0 = __ldg(&g_A[r0]), Bi0 = __ldg(&g_B[r0]), th0 = __ldg(&g_thE[r0]);
    float Ai1 = __ldg(&g_A[r1]), Bi1 = __ldg(&g_B[r1]), th1 = __ldg(&g_thE[r1]);
    const int* adj0 = adj + (size_t)r0 * NV + jbase;
    const int* adj1 = adj + (size_t)r1 * NV + jbase;

    float acc[8][4];
#pragma unroll
    for (int n = 0; n < 8; n++)
#pragma unroll
        for (int q = 0; q < 4; q++) acc[n][q] = 0.f;

    // prefetch k-tile 0 adjacency
    int jc = tg * 2;
    int2 p00 = __ldg((const int2*)(adj0 + jc));
    int2 p08 = __ldg((const int2*)(adj0 + jc + 8));
    int2 p10 = __ldg((const int2*)(adj1 + jc));
    int2 p18 = __ldg((const int2*)(adj1 + jc + 8));

    for (int kt = 0; kt < 32; ++kt) {
        int j0 = kt * 16 + tg * 2;          // local j of this thread's first col
        int2 c00 = p00, c08 = p08, c10 = p10, c18 = p18;
        if (kt < 31) {
            int jn = j0 + 16;
            p00 = __ldg((const int2*)(adj0 + jn));
            p08 = __ldg((const int2*)(adj0 + jn + 8));
            p10 = __ldg((const int2*)(adj1 + jn));
            p18 = __ldg((const int2*)(adj1 + jn + 8));
        }
        float2 e10 = *(const float2*)&sE1[j0];
        float2 e18 = *(const float2*)&sE1[j0 + 8];
        float2 e20 = *(const float2*)&sE2[j0];
        float2 e28 = *(const float2*)&sE2[j0 + 8];

        uint32_t a0h, a0l, a1h, a1l, a2h, a2l, a3h, a3l;
        build_pair(c00.x, c00.y, e10.x, e10.y, e20.x, e20.y, Ai0, Bi0, th0, a0h, a0l);
        build_pair(c10.x, c10.y, e10.x, e10.y, e20.x, e20.y, Ai1, Bi1, th1, a1h, a1l);
        build_pair(c08.x, c08.y, e18.x, e18.y, e28.x, e28.y, Ai0, Bi0, th0, a2h, a2l);
        build_pair(c18.x, c18.y, e18.x, e18.y, e28.x, e28.y, Ai1, Bi1, th1, a3h, a3l);

        size_t bj = (size_t)(jbase + j0) >> 1;   // u32-pair index along j
#pragma unroll
        for (int n = 0; n < 8; n++) {
            int c = n * 8 + gid;
            const uint2* bp = &g_WhC[(size_t)c * (NV / 2) + bj];
            uint2 b0 = __ldg(bp);        // {hi, lo} for j0, j0+1
            uint2 b1 = __ldg(bp + 4);    // {hi, lo} for j0+8, j0+9
            MMA_BF16(acc[n][0], acc[n][1], acc[n][2], acc[n][3],
                     a0h, a1h, a2h, a3h, b0.x, b1.x);
            MMA_BF16(acc[n][0], acc[n][1], acc[n][2], acc[n][3],
                     a0h, a1h, a2h, a3h, b0.y, b1.y);
            MMA_BF16(acc[n][0], acc[n][1], acc[n][2], acc[n][3],
                     a0l, a1l, a2l, a3l, b0.x, b1.x);
        }
    }

    // epilogue: fragment rows r0/r1, cols n*8 + tg*2 (+1)
    float* dst = g_part[jseg];
#pragma unroll
    for (int n = 0; n < 8; n++) {
        int c = n * 8 + tg * 2;
        *(float2*)&dst[(size_t)r0 * 64 + c] = make_float2(acc[n][0], acc[n][1]);
        *(float2*)&dst[(size_t)r1 * 64 + c] = make_float2(acc[n][2], acc[n][3]);
    }
}

// ---------------- K4: combine 8 partials, scale, ELU ----------------
__global__ __launch_bounds__(256) void k4_out(float* __restrict__ out) {
    int v4 = blockIdx.x * 256 + threadIdx.x;
    float4 s = __ldg(&((const float4*)g_part[0])[v4]);
#pragma unroll
    for (int p = 1; p < 8; p++) {
        float4 t = __ldg(&((const float4*)g_part[p])[v4]);
        s.x += t.x; s.y += t.y; s.z += t.z; s.w += t.w;
    }
    int i = v4 >> 4;
    float di = g_dinv[i];
    s.x *= di; s.y *= di; s.z *= di; s.w *= di;
    s.x = s.x > 0.f ? s.x : (__expf(s.x) - 1.f);
    s.y = s.y > 0.f ? s.y : (__expf(s.y) - 1.f);
    s.z = s.z > 0.f ? s.z : (__expf(s.z) - 1.f);
    s.w = s.w > 0.f ? s.w : (__expf(s.w) - 1.f);
    ((float4*)out)[v4] = s;
}

// ---------------- launch ----------------
extern "C" void kernel_launch(void* const* d_in, const int* in_sizes, int n_in,
                              void* d_out, int out_size) {
    const float* H = (const float*)d_in[0];
    const int* adj = (const int*)d_in[1];
    const float* W = (const float*)d_in[2];
    const float* a = (const float*)d_in[3];
    float* out = (float*)d_out;

    k1_wh<<<256, 256>>>(H, W, a);
    kT_split<<<64, 256>>>();
    k2_denom<<<256, 256>>>();
    k3_main<<<256, 256>>>(adj);
    k4_out<<<256, 256>>>(out);
}

// round 9
// speedup vs baseline: 1.3483x; 1.0509x over previous
#include <cuda_runtime.h>
#include <cstdint>

#define NV 4096
#define ALPHA 0.2f

// ---------------- device scratch ----------------
__device__ float g_Wh[NV * 64];
__device__ float g_e1[NV], g_e2[NV];
__device__ float g_E1[NV], g_E2[NV];
__device__ float g_A[NV], g_B[NV], g_thE[NV], g_dinv[NV];
__device__ float g_part[16][NV * 64];
__device__ uint2 g_WhC[64 * (NV / 2)];   // [c][j/2] = {bf16x2 hi pair, bf16x2 lo pair}

// ---------------- K1: Wh = H@W + e1/e2 + E1/E2 (16-row blocks, grid 256) -----
__global__ __launch_bounds__(256) void k1_wh(const float* __restrict__ H,
                                             const float* __restrict__ W,
                                             const float* __restrict__ a) {
    __shared__ float Hs[16][68];
    __shared__ float Ws[64][64];
    int tid = threadIdx.x;
    int tr = tid >> 4;
    int tc = tid & 15;
    int row0 = blockIdx.x * 16;

    unsigned long long acc[2] = {0ull, 0ull};

    for (int kk = 0; kk < 256; kk += 64) {
#pragma unroll
        for (int t = 0; t < 4; t++) {
            int u = tid + t * 256;
            int r = u >> 4, c4 = u & 15;
            *(float4*)&Ws[r][c4 * 4] = *(const float4*)&W[(size_t)(kk + r) * 64 + c4 * 4];
        }
        *(float4*)&Hs[tr][tc * 4] = *(const float4*)&H[(size_t)(row0 + tr) * 256 + kk + tc * 4];
        __syncthreads();
#pragma unroll 8
        for (int k = 0; k < 64; k++) {
            float4 w4 = *(const float4*)&Ws[k][tc * 4];
            unsigned long long w01, w23, hp;
            asm("mov.b64 %0, {%1, %2};" : "=l"(w01) : "f"(w4.x), "f"(w4.y));
            asm("mov.b64 %0, {%1, %2};" : "=l"(w23) : "f"(w4.z), "f"(w4.w));
            float h = Hs[tr][k];
            asm("mov.b64 %0, {%1, %1};" : "=l"(hp) : "f"(h));
            asm("fma.rn.f32x2 %0, %1, %2, %0;" : "+l"(acc[0]) : "l"(hp), "l"(w01));
            asm("fma.rn.f32x2 %0, %1, %2, %0;" : "+l"(acc[1]) : "l"(hp), "l"(w23));
        }
        __syncthreads();
    }

    float v0 = __uint_as_float((uint32_t)acc[0]);
    float v1 = __uint_as_float((uint32_t)(acc[0] >> 32));
    float v2 = __uint_as_float((uint32_t)acc[1]);
    float v3 = __uint_as_float((uint32_t)(acc[1] >> 32));

    int i = row0 + tr;
    *(float4*)&g_Wh[(size_t)i * 64 + tc * 4] = make_float4(v0, v1, v2, v3);

    float p1 = v0 * __ldg(&a[tc * 4]) + v1 * __ldg(&a[tc * 4 + 1])
             + v2 * __ldg(&a[tc * 4 + 2]) + v3 * __ldg(&a[tc * 4 + 3]);
    float p2 = v0 * __ldg(&a[64 + tc * 4]) + v1 * __ldg(&a[64 + tc * 4 + 1])
             + v2 * __ldg(&a[64 + tc * 4 + 2]) + v3 * __ldg(&a[64 + tc * 4 + 3]);
#pragma unroll
    for (int off = 1; off < 16; off <<= 1) {
        p1 += __shfl_xor_sync(0xffffffffu, p1, off);
        p2 += __shfl_xor_sync(0xffffffffu, p2, off);
    }
    if (tc == 0) {
        g_e1[i] = p1;
        g_e2[i] = p2;
        g_E1[i] = __expf(p2);
        g_E2[i] = __expf(ALPHA * p2);
    }
}

// ---------------- kT: transpose + bf16 hi/lo split of Wh -> g_WhC ------------
__global__ __launch_bounds__(256) void kT_split() {
    __shared__ float t[64][65];
    int tid = threadIdx.x;
    int j0 = blockIdx.x * 64;
#pragma unroll
    for (int q = 0; q < 4; q++) {
        int u = tid + q * 256;
        int r = u >> 4, c4 = u & 15;
        float4 vv = *(const float4*)&g_Wh[(size_t)(j0 + r) * 64 + c4 * 4];
        t[r][c4 * 4 + 0] = vv.x; t[r][c4 * 4 + 1] = vv.y;
        t[r][c4 * 4 + 2] = vv.z; t[r][c4 * 4 + 3] = vv.w;
    }
    __syncthreads();
    int c = tid >> 2;
    int jq = (tid & 3) * 16;
    uint2 outv[8];
#pragma unroll
    for (int s = 0; s < 8; s++) {
        float w0 = t[jq + s * 2 + 0][c];
        float w1 = t[jq + s * 2 + 1][c];
        uint32_t hp;
        asm("cvt.rn.bf16x2.f32 %0, %1, %2;" : "=r"(hp) : "f"(w1), "f"(w0));
        float h0 = __uint_as_float(hp << 16);
        float h1 = __uint_as_float(hp & 0xffff0000u);
        float l0 = w0 - h0, l1 = w1 - h1;
        uint32_t lp;
        asm("cvt.rn.bf16x2.f32 %0, %1, %2;" : "=r"(lp) : "f"(l1), "f"(l0));
        outv[s] = make_uint2(hp, lp);
    }
    uint2* dst = &g_WhC[(size_t)c * (NV / 2) + ((j0 + jq) >> 1)];
#pragma unroll
    for (int s = 0; s < 8; s++) dst[s] = outv[s];
}

// ---------------- K2: per-row m, A, B, thE, 1/denominator ----------------
__global__ __launch_bounds__(256) void k2_denom() {
    __shared__ float sE1[NV];
    __shared__ float sE2[NV];
    __shared__ float red[8];
    int tid = threadIdx.x;
#pragma unroll
    for (int t = 0; t < 4; t++) {
        ((float4*)sE1)[tid + t * 256] = ((const float4*)g_E1)[tid + t * 256];
        ((float4*)sE2)[tid + t * 256] = ((const float4*)g_E2)[tid + t * 256];
    }
    float mx = -1e30f;
#pragma unroll
    for (int t = 0; t < 4; t++) {
        float4 v = ((const float4*)g_e2)[tid + t * 256];
        mx = fmaxf(fmaxf(mx, v.x), fmaxf(fmaxf(v.y, v.z), v.w));
    }
#pragma unroll
    for (int o = 16; o > 0; o >>= 1) mx = fmaxf(mx, __shfl_xor_sync(0xffffffffu, mx, o));
    if ((tid & 31) == 0) red[tid >> 5] = mx;
    __syncthreads();
    float e2max = red[0];
#pragma unroll
    for (int w = 1; w < 8; w++) e2max = fmaxf(e2max, red[w]);

    int il = tid >> 4;
    int sub = tid & 15;
    int i = blockIdx.x * 16 + il;
    float e1v = g_e1[i];
    float s = e1v + e2max;
    float m = s > 0.f ? s : ALPHA * s;
    float A = __expf(e1v - m);
    float B = __expf(ALPHA * e1v - m);
    float thE = __expf(-e1v);

    float d = 0.f;
#pragma unroll 4
    for (int t = 0; t < 64; t++) {
        int j = sub * 4 + t * 64;
        float4 E1v = *(const float4*)&sE1[j];
        float4 E2v = *(const float4*)&sE2[j];
        d += (E1v.x > thE) ? A * E1v.x : B * E2v.x;
        d += (E1v.y > thE) ? A * E1v.y : B * E2v.y;
        d += (E1v.z > thE) ? A * E1v.z : B * E2v.z;
        d += (E1v.w > thE) ? A * E1v.w : B * E2v.w;
    }
#pragma unroll
    for (int o = 8; o > 0; o >>= 1) d += __shfl_xor_sync(0xffffffffu, d, o);
    if (sub == 0) {
        g_A[i] = A; g_B[i] = B; g_thE[i] = thE;
        g_dinv[i] = 1.f / d;
    }
}

// ---------------- A-fragment pair build ----------------
__device__ __forceinline__ void build_pair(int ax, int ay,
                                           float e1x, float e1y,
                                           float e2x, float e2y,
                                           float Ai, float Bi, float th,
                                           uint32_t& hi, uint32_t& lo) {
    float w0 = (ax > 0) ? ((e1x > th) ? Ai * e1x : Bi * e2x) : 0.f;
    float w1 = (ay > 0) ? ((e1y > th) ? Ai * e1y : Bi * e2y) : 0.f;
    uint32_t h;
    asm("cvt.rn.bf16x2.f32 %0, %1, %2;" : "=r"(h) : "f"(w1), "f"(w0));
    float h0 = __uint_as_float(h << 16);
    float h1 = __uint_as_float(h & 0xffff0000u);
    float l0 = w0 - h0, l1 = w1 - h1;
    uint32_t l;
    asm("cvt.rn.bf16x2.f32 %0, %1, %2;" : "=r"(l) : "f"(l1), "f"(l0));
    hi = h; lo = l;
}

#define MMA_BF16(c0, c1, c2, c3, a0, a1, a2, a3, b0, b1)                        \
    asm("mma.sync.aligned.m16n8k16.row.col.f32.bf16.bf16.f32 "                 \
        "{%0,%1,%2,%3}, {%4,%5,%6,%7}, {%8,%9}, {%0,%1,%2,%3};"                \
        : "+f"(c0), "+f"(c1), "+f"(c2), "+f"(c3)                               \
        : "r"(a0), "r"(a1), "r"(a2), "r"(a3), "r"(b0), "r"(b1))

// ---------------- K3: masked GEMM on tensor cores, M=32/warp, hoisted B ------
// Grid 512 = 32 rb (128 i) x 16 jt (256 j). 4 warps/CTA, warp = 32 rows.
// 16 k-tiles of 16 j. No smem, no syncs. B frags amortized over 2 m-tiles.
__global__ __launch_bounds__(128, 3) void k3_main(const int* __restrict__ adj) {
    int tid = threadIdx.x;
    int warp = tid >> 5, lane = tid & 31;
    int gid = lane >> 2, tg = lane & 3;
    int rb = blockIdx.x >> 4;
    int jt = blockIdx.x & 15;
    int jbase = jt << 8;

    int base = rb * 128 + warp * 32;
    int r0 = base + gid, r1 = r0 + 8, r2 = r0 + 16, r3 = r0 + 24;
    float Ai0 = __ldg(&g_A[r0]), Bi0 = __ldg(&g_B[r0]), th0 = __ldg(&g_thE[r0]);
    float Ai1 = __ldg(&g_A[r1]), Bi1 = __ldg(&g_B[r1]), th1 = __ldg(&g_thE[r1]);
    float Ai2 = __ldg(&g_A[r2]), Bi2 = __ldg(&g_B[r2]), th2 = __ldg(&g_thE[r2]);
    float Ai3 = __ldg(&g_A[r3]), Bi3 = __ldg(&g_B[r3]), th3 = __ldg(&g_thE[r3]);
    const int* a0p = adj + (size_t)r0 * NV + jbase;
    const int* a1p = adj + (size_t)r1 * NV + jbase;
    const int* a2p = adj + (size_t)r2 * NV + jbase;
    const int* a3p = adj + (size_t)r3 * NV + jbase;

    float acc[2][8][4];
#pragma unroll
    for (int m = 0; m < 2; m++)
#pragma unroll
        for (int n = 0; n < 8; n++)
#pragma unroll
            for (int q = 0; q < 4; q++) acc[m][n][q] = 0.f;

    // prefetch k-tile 0 adjacency (4 rows x 2 j-groups)
    int jc = tg * 2;
    int2 p0a = __ldg((const int2*)(a0p + jc)), p0b = __ldg((const int2*)(a0p + jc + 8));
    int2 p1a = __ldg((const int2*)(a1p + jc)), p1b = __ldg((const int2*)(a1p + jc + 8));
    int2 p2a = __ldg((const int2*)(a2p + jc)), p2b = __ldg((const int2*)(a2p + jc + 8));
    int2 p3a = __ldg((const int2*)(a3p + jc)), p3b = __ldg((const int2*)(a3p + jc + 8));

    for (int kt = 0; kt < 16; ++kt) {
        int j0 = kt * 16 + tg * 2;       // local j within CTA tile
        int gj = jbase + j0;             // global j

        // ---- hoisted B loads (16 independent LDG.64) ----
        uint2 b0[8], b1[8];
        size_t bj = (size_t)gj >> 1;
#pragma unroll
        for (int n = 0; n < 8; n++) {
            const uint2* bp = &g_WhC[(size_t)(n * 8 + gid) * (NV / 2) + bj];
            b0[n] = __ldg(bp);
            b1[n] = __ldg(bp + 4);
        }
        // ---- E loads ----
        float2 e10 = __ldg((const float2*)&g_E1[gj]);
        float2 e18 = __ldg((const float2*)&g_E1[gj + 8]);
        float2 e20 = __ldg((const float2*)&g_E2[gj]);
        float2 e28 = __ldg((const float2*)&g_E2[gj + 8]);

        int2 c0a = p0a, c0b = p0b, c1a = p1a, c1b = p1b;
        int2 c2a = p2a, c2b = p2b, c3a = p3a, c3b = p3b;
        if (kt < 15) {
            int jn = j0 + 16;
            p0a = __ldg((const int2*)(a0p + jn)); p0b = __ldg((const int2*)(a0p + jn + 8));
            p1a = __ldg((const int2*)(a1p + jn)); p1b = __ldg((const int2*)(a1p + jn + 8));
            p2a = __ldg((const int2*)(a2p + jn)); p2b = __ldg((const int2*)(a2p + jn + 8));
            p3a = __ldg((const int2*)(a3p + jn)); p3b = __ldg((const int2*)(a3p + jn + 8));
        }

        // ---- build A fragments for both m-tiles ----
        uint32_t ah[2][4], al[2][4];
        build_pair(c0a.x, c0a.y, e10.x, e10.y, e20.x, e20.y, Ai0, Bi0, th0, ah[0][0], al[0][0]);
        build_pair(c1a.x, c1a.y, e10.x, e10.y, e20.x, e20.y, Ai1, Bi1, th1, ah[0][1], al[0][1]);
        build_pair(c0b.x, c0b.y, e18.x, e18.y, e28.x, e28.y, Ai0, Bi0, th0, ah[0][2], al[0][2]);
        build_pair(c1b.x, c1b.y, e18.x, e18.y, e28.x, e28.y, Ai1, Bi1, th1, ah[0][3], al[0][3]);
        build_pair(c2a.x, c2a.y, e10.x, e10.y, e20.x, e20.y, Ai2, Bi2, th2, ah[1][0], al[1][0]);
        build_pair(c3a.x, c3a.y, e10.x, e10.y, e20.x, e20.y, Ai3, Bi3, th3, ah[1][1], al[1][1]);
        build_pair(c2b.x, c2b.y, e18.x, e18.y, e28.x, e28.y, Ai2, Bi2, th2, ah[1][2], al[1][2]);
        build_pair(c3b.x, c3b.y, e18.x, e18.y, e28.x, e28.y, Ai3, Bi3, th3, ah[1][3], al[1][3]);

        // ---- MMAs: 8 n-tiles x 2 m-tiles x 3 ----
#pragma unroll
        for (int n = 0; n < 8; n++) {
#pragma unroll
            for (int m = 0; m < 2; m++) {
                MMA_BF16(acc[m][n][0], acc[m][n][1], acc[m][n][2], acc[m][n][3],
                         ah[m][0], ah[m][1], ah[m][2], ah[m][3], b0[n].x, b1[n].x);
                MMA_BF16(acc[m][n][0], acc[m][n][1], acc[m][n][2], acc[m][n][3],
                         ah[m][0], ah[m][1], ah[m][2], ah[m][3], b0[n].y, b1[n].y);
                MMA_BF16(acc[m][n][0], acc[m][n][1], acc[m][n][2], acc[m][n][3],
                         al[m][0], al[m][1], al[m][2], al[m][3], b0[n].x, b1[n].x);
            }
        }
    }

    // ---- epilogue ----
    float* dst = g_part[jt];
#pragma unroll
    for (int n = 0; n < 8; n++) {
        int c = n * 8 + tg * 2;
        *(float2*)&dst[(size_t)r0 * 64 + c] = make_float2(acc[0][n][0], acc[0][n][1]);
        *(float2*)&dst[(size_t)r1 * 64 + c] = make_float2(acc[0][n][2], acc[0][n][3]);
        *(float2*)&dst[(size_t)r2 * 64 + c] = make_float2(acc[1][n][0], acc[1][n][1]);
        *(float2*)&dst[(size_t)r3 * 64 + c] = make_float2(acc[1][n][2], acc[1][n][3]);
    }
}

// ---------------- K4: combine 16 partials, scale, ELU ----------------
__global__ __launch_bounds__(256) void k4_out(float* __restrict__ out) {
    int v4 = blockIdx.x * 256 + threadIdx.x;
    float4 s = __ldg(&((const float4*)g_part[0])[v4]);
#pragma unroll
    for (int p = 1; p < 16; p++) {
        float4 t = __ldg(&((const float4*)g_part[p])[v4]);
        s.x += t.x; s.y += t.y; s.z += t.z; s.w += t.w;
    }
    int i = v4 >> 4;
    float di = g_dinv[i];
    s.x *= di; s.y *= di; s.z *= di; s.w *= di;
    s.x = s.x > 0.f ? s.x : (__expf(s.x) - 1.f);
    s.y = s.y > 0.f ? s.y : (__expf(s.y) - 1.f);
    s.z = s.z > 0.f ? s.z : (__expf(s.z) - 1.f);
    s.w = s.w > 0.f ? s.w : (__expf(s.w) - 1.f);
    ((float4*)out)[v4] = s;
}

// ---------------- launch ----------------
extern "C" void kernel_launch(void* const* d_in, const int* in_sizes, int n_in,
                              void* d_out, int out_size) {
    const float* H = (const float*)d_in[0];
    const int* adj = (const int*)d_in[1];
    const float* W = (const float*)d_in[2];
    const float* a = (const float*)d_in[3];
    float* out = (float*)d_out;

    k1_wh<<<256, 256>>>(H, W, a);
    kT_split<<<64, 256>>>();
    k2_denom<<<256, 256>>>();
    k3_main<<<512, 128>>>(adj);
    k4_out<<<256, 256>>>(out);
}